// round 1
// baseline (speedup 1.0000x reference)
#include <cuda_runtime.h>
#include <cstdint>

#define BB  256
#define LL  512
#define DD  64
#define NID 10000
#define MAXC 513   // counts range 0..512 inclusive

// Lookup table: g(a)[e] = sum_d relu(a*W1[d] + b1[d]) * W2[e][d] + b2[e]
// Output row for a position with counts (a0, a1) is g(a0) + g(a1).
__device__ float g_table[MAXC * DD];

// ---------------------------------------------------------------------------
// Kernel 1: build the 513 x 64 table. 513 blocks x 64 threads, ~2 us.
// ---------------------------------------------------------------------------
__global__ void build_table(const float* __restrict__ W1,
                            const float* __restrict__ b1,
                            const float* __restrict__ W2,
                            const float* __restrict__ b2) {
    __shared__ float h[DD];
    const int a = blockIdx.x;     // count value 0..512
    const int e = threadIdx.x;    // output channel

    // W1 is (D,1) -> W1[e]
    float hv = fmaf((float)a, W1[e], b1[e]);
    h[e] = hv > 0.0f ? hv : 0.0f;
    __syncthreads();

    float s = b2[e];
    const float* w2row = W2 + e * DD;   // out[e] = sum_d h[d] * W2[e,d]
    #pragma unroll 16
    for (int d = 0; d < DD; ++d)
        s = fmaf(h[d], w2row[d], s);
    g_table[a * DD + e] = s;
}

// ---------------------------------------------------------------------------
// Kernel 2: per-batch histogram counting + table-lookup encode + store.
// One CTA per batch sample, 512 threads (one per sequence position).
//   hist[id]: low 16 bits = count of id in src seq, high 16 bits = in dst seq.
// ---------------------------------------------------------------------------
__global__ void __launch_bounds__(512, 1) count_encode(
        const int* __restrict__ src,
        const int* __restrict__ dst,
        float* __restrict__ out) {
    __shared__ uint32_t hist[NID];   // 40000 B
    __shared__ uint32_t cs[LL];      // packed (a0 | a1<<16) per src position
    __shared__ uint32_t cd[LL];      // packed per dst position

    const int b = blockIdx.x;
    const int t = threadIdx.x;

    // zero histogram
    #pragma unroll
    for (int i = t; i < NID; i += 512) hist[i] = 0u;

    const int sid = src[b * LL + t];
    const int did = dst[b * LL + t];
    __syncthreads();

    atomicAdd(&hist[sid], 1u);
    atomicAdd(&hist[did], 1u << 16);
    __syncthreads();

    // counts for this position; id==0 is padding -> force (0,0) lookup
    uint32_t hs = (sid == 0) ? 0u : hist[sid];
    uint32_t hd = (did == 0) ? 0u : hist[did];
    cs[t] = hs;
    cd[t] = hd;
    __syncthreads();

    // Write phase: float4-coalesced. 16 lanes cover one 64-float row,
    // 512 threads cover 32 rows per iteration, 16 iterations for L=512.
    const float4* __restrict__ T = (const float4*)g_table;
    const int lane = t & 15;
    float4* __restrict__ osrc = (float4*)(out + (size_t)b * LL * DD);
    float4* __restrict__ odst = (float4*)(out + (size_t)BB * LL * DD
                                              + (size_t)b * LL * DD);

    for (int r = (t >> 4); r < LL; r += 32) {
        uint32_t c = cs[r];
        float4 v0 = T[(c & 0xFFFFu) * 16 + lane];
        float4 v1 = T[(c >> 16)    * 16 + lane];
        float4 w;
        w.x = v0.x + v1.x; w.y = v0.y + v1.y;
        w.z = v0.z + v1.z; w.w = v0.w + v1.w;
        osrc[r * 16 + lane] = w;

        c = cd[r];
        v0 = T[(c & 0xFFFFu) * 16 + lane];
        v1 = T[(c >> 16)    * 16 + lane];
        w.x = v0.x + v1.x; w.y = v0.y + v1.y;
        w.z = v0.z + v1.z; w.w = v0.w + v1.w;
        odst[r * 16 + lane] = w;
    }
}

// ---------------------------------------------------------------------------
// Harness entry point. Inputs in metadata order:
//   0: src_ids (B*L int32)  1: dst_ids (B*L int32)
//   2: W1 (D*1 f32)  3: b1 (D f32)  4: W2 (D*D f32)  5: b2 (D f32)
// Output: [src_feat | dst_feat], each B*L*D f32.
// ---------------------------------------------------------------------------
extern "C" void kernel_launch(void* const* d_in, const int* in_sizes, int n_in,
                              void* d_out, int out_size) {
    const int*   src = (const int*)d_in[0];
    const int*   dst = (const int*)d_in[1];
    const float* W1  = (const float*)d_in[2];
    const float* b1  = (const float*)d_in[3];
    const float* W2  = (const float*)d_in[4];
    const float* b2  = (const float*)d_in[5];
    float* out = (float*)d_out;

    build_table<<<MAXC, DD>>>(W1, b1, W2, b2);
    count_encode<<<BB, 512>>>(src, dst, out);
}

// round 2
// speedup vs baseline: 1.3418x; 1.3418x over previous
#include <cuda_runtime.h>
#include <cstdint>

#define BB  256
#define LL  512
#define DD  64
#define NID 10000
#define TMAX 32          // smem table rows (counts beyond this take the direct path)

// dynamic smem layout (bytes):
//   [0      , 16384) W2s    : 64x64 f32
//   [16384  , 24576) table  : 32x64 f32   (g(a) rows, a in [0, nrows))
//   [24576  , 32768) h_all  : 32x64 f32   (relu(a*w1+b1) rows)
//   [32768  , 34816) cs     : 512 u32 packed (src_cnt | dst_cnt<<16) per src pos
//   [34816  , 36864) cd     : 512 u32 per dst pos
//   [36864  , 76864) hist   : 10000 u32 (lo16 = count in src, hi16 = count in dst)
//   [76864  , 76868) maxc
#define SMEM_BYTES 76880

// Direct computation of g(a)[e..e+3] for the (never-in-practice) case a >= nrows.
__device__ __forceinline__ float4 g_direct(uint32_t a, int lane,
                                           const float* __restrict__ W1,
                                           const float* __restrict__ b1,
                                           const float* __restrict__ b2,
                                           const float* __restrict__ W2s) {
    float4 s = ((const float4*)b2)[lane];
    const int e = lane * 4;
    for (int d = 0; d < DD; ++d) {
        float hv = fmaf((float)a, W1[d], b1[d]);
        hv = hv > 0.f ? hv : 0.f;
        s.x = fmaf(hv, W2s[(e + 0) * DD + d], s.x);
        s.y = fmaf(hv, W2s[(e + 1) * DD + d], s.y);
        s.z = fmaf(hv, W2s[(e + 2) * DD + d], s.z);
        s.w = fmaf(hv, W2s[(e + 3) * DD + d], s.w);
    }
    return s;
}

__global__ void __launch_bounds__(512, 2) fused_encode(
        const int* __restrict__ src,
        const int* __restrict__ dst,
        const float* __restrict__ W1,
        const float* __restrict__ b1,
        const float* __restrict__ W2,
        const float* __restrict__ b2,
        float* __restrict__ out) {
    extern __shared__ unsigned char sraw[];
    float*    W2s   = (float*)(sraw);
    float*    table = (float*)(sraw + 16384);
    float*    h_all = (float*)(sraw + 24576);
    uint32_t* cs    = (uint32_t*)(sraw + 32768);
    uint32_t* cd    = (uint32_t*)(sraw + 34816);
    uint32_t* hist  = (uint32_t*)(sraw + 36864);
    uint32_t* maxc  = (uint32_t*)(sraw + 76864);

    const int t = threadIdx.x;
    const int b = blockIdx.x;

    // --- phase 0: zero histogram (128-bit), stage W2 into smem, load ids ---
    const uint4 z = make_uint4(0u, 0u, 0u, 0u);
    #pragma unroll
    for (int i = t; i < NID / 4; i += 512) ((uint4*)hist)[i] = z;
    if (t == 0) *maxc = 0u;
    #pragma unroll
    for (int i = t; i < (DD * DD) / 4; i += 512)
        ((float4*)W2s)[i] = ((const float4*)W2)[i];

    const int sid = src[b * LL + t];
    const int did = dst[b * LL + t];
    __syncthreads();

    // --- phase 1: packed dual histogram ---
    atomicAdd(&hist[sid], 1u);
    atomicAdd(&hist[did], 0x10000u);
    __syncthreads();

    // --- phase 2: gather per-position counts, find max count in this batch ---
    const uint32_t hs = sid ? hist[sid] : 0u;   // padding id 0 -> (0,0)
    const uint32_t hd = did ? hist[did] : 0u;
    cs[t] = hs;
    cd[t] = hd;
    uint32_t m = max(max(hs & 0xFFFFu, hs >> 16), max(hd & 0xFFFFu, hd >> 16));
    m = __reduce_max_sync(0xFFFFFFFFu, m);
    if ((t & 31) == 0) atomicMax(maxc, m);
    __syncthreads();

    const int nrows = min((int)(*maxc) + 1, TMAX);

    // --- phase 3: build g-table rows 0..nrows-1 in smem ---
    for (int idx = t; idx < nrows * DD; idx += 512) {
        const int a = idx >> 6, d = idx & 63;
        const float hv = fmaf((float)a, W1[d], b1[d]);
        h_all[idx] = hv > 0.f ? hv : 0.f;
    }
    __syncthreads();
    for (int idx = t; idx < nrows * DD; idx += 512) {
        const int a = idx >> 6, e = idx & 63;
        float s = b2[e];
        const float* hr = h_all + a * DD;
        const float* wr = W2s + e * DD;
        #pragma unroll 16
        for (int d = 0; d < DD; ++d) s = fmaf(hr[d], wr[d], s);
        table[idx] = s;
    }
    __syncthreads();

    // --- phase 4: streamed, float4-coalesced output. 16 lanes per 64-f row,
    // 512 threads cover 32 rows/iter, 16 iters for L=512. ---
    const int lane = t & 15;
    const float4* T4 = (const float4*)table;
    float4* __restrict__ osrc = (float4*)(out + (size_t)b * LL * DD);
    float4* __restrict__ odst = (float4*)(out + (size_t)BB * LL * DD
                                              + (size_t)b * LL * DD);

    for (int r = (t >> 4); r < LL; r += 32) {
        uint32_t c = cs[r];
        uint32_t a0 = c & 0xFFFFu, a1 = c >> 16;
        float4 v0 = (a0 < (uint32_t)nrows) ? T4[a0 * 16 + lane]
                                           : g_direct(a0, lane, W1, b1, b2, W2s);
        float4 v1 = (a1 < (uint32_t)nrows) ? T4[a1 * 16 + lane]
                                           : g_direct(a1, lane, W1, b1, b2, W2s);
        float4 w;
        w.x = v0.x + v1.x; w.y = v0.y + v1.y;
        w.z = v0.z + v1.z; w.w = v0.w + v1.w;
        osrc[r * 16 + lane] = w;

        c = cd[r];
        a0 = c & 0xFFFFu; a1 = c >> 16;
        v0 = (a0 < (uint32_t)nrows) ? T4[a0 * 16 + lane]
                                    : g_direct(a0, lane, W1, b1, b2, W2s);
        v1 = (a1 < (uint32_t)nrows) ? T4[a1 * 16 + lane]
                                    : g_direct(a1, lane, W1, b1, b2, W2s);
        w.x = v0.x + v1.x; w.y = v0.y + v1.y;
        w.z = v0.z + v1.z; w.w = v0.w + v1.w;
        odst[r * 16 + lane] = w;
    }
}

extern "C" void kernel_launch(void* const* d_in, const int* in_sizes, int n_in,
                              void* d_out, int out_size) {
    const int*   src = (const int*)d_in[0];
    const int*   dst = (const int*)d_in[1];
    const float* W1  = (const float*)d_in[2];
    const float* b1  = (const float*)d_in[3];
    const float* W2  = (const float*)d_in[4];
    const float* b2  = (const float*)d_in[5];
    float* out = (float*)d_out;

    cudaFuncSetAttribute(fused_encode,
                         cudaFuncAttributeMaxDynamicSharedMemorySize, SMEM_BYTES);
    fused_encode<<<BB, 512, SMEM_BYTES>>>(src, dst, W1, b1, W2, b2, out);
}